// round 5
// baseline (speedup 1.0000x reference)
#include <cuda_runtime.h>

// labels[c] = argmax_q code_book[c][q]  (first-occurrence tie-break)
//   == reference argmin_q (tn[b,l,c] - cbn[c,q]): tn is constant over q and
//   cbn is a monotone strictly-increasing affine map of code_book, so the
//   GEMM, both LayerNorms, and the (B,L,C,Q) distance tensor are dead code.
// Output (B,L,C)=(4,512,256) f32: every row = labels[0..255].
//
// Grid = 32 column-groups x 4 row-groups = 128 blocks (< 148 SMs: ONE wave,
// one CTA per SM). Block (cg, rg): warp w computes argmax of codebook row
// 8cg+w (REDUX.MAX on sortable bits + ballot/ffs for first index), then each
// thread writes cols [8cg,8cg+8) for output rows rg*512 + t and rg*512 + t + 256.

static constexpr int C    = 256;
static constexpr int Qdim = 256;

__global__ void __launch_bounds__(256, 1)
fused_rpq_kernel(const float* __restrict__ cb, float4* __restrict__ out) {
    __shared__ __align__(16) float lab[8];

    const int tid  = threadIdx.x;
    const int lane = tid & 31;
    const int warp = tid >> 5;
    const int cg   = blockIdx.x & 31;   // codebook rows [8cg, 8cg+8)
    const int rg   = blockIdx.x >> 5;   // output rows [512rg, 512rg+512)

    // ---- Phase 1: warp w -> argmax of codebook row 8cg+w ----
    {
        const int row = cg * 8 + warp;
        const float4* __restrict__ rp =
            reinterpret_cast<const float4*>(cb + row * Qdim) + lane * 2;
        const float4 a = __ldg(rp);
        const float4 b = __ldg(rp + 1);

        // per-lane best over q = 8*lane .. 8*lane+7 (strict > keeps first idx)
        float bv = a.x; int bi = 0;
        if (a.y > bv) { bv = a.y; bi = 1; }
        if (a.z > bv) { bv = a.z; bi = 2; }
        if (a.w > bv) { bv = a.w; bi = 3; }
        if (b.x > bv) { bv = b.x; bi = 4; }
        if (b.y > bv) { bv = b.y; bi = 5; }
        if (b.z > bv) { bv = b.z; bi = 6; }
        if (b.w > bv) { bv = b.w; bi = 7; }
        bi += lane * 8;

        // order-preserving bijection f32 -> u32 (flip sign bit for +, all for -)
        const unsigned u    = __float_as_uint(bv);
        const unsigned skey = u ^ (unsigned)(((int)u >> 31) | 0x80000000);

        const unsigned m    = __reduce_max_sync(0xffffffffu, skey);   // REDUX.MAX
        const unsigned mask = __ballot_sync(0xffffffffu, skey == m);
        const int src       = __ffs(mask) - 1;        // lowest lane = lowest q block
        const int win       = __shfl_sync(0xffffffffu, bi, src);
        if (lane == 0) lab[warp] = (float)win;
    }
    __syncthreads();

    // ---- Phase 2: thread t writes rows 512rg+t and 512rg+t+256 ----
    const float4* __restrict__ lab4 = reinterpret_cast<const float4*>(lab);
    const float4 v0 = lab4[0];
    const float4 v1 = lab4[1];
    const int idx0 = (rg * 512 + tid) * (C / 4) + cg * 2;   // float4 index
    out[idx0]           = v0;
    out[idx0 + 1]       = v1;
    out[idx0 + 16384]   = v0;   // +256 rows * 64 float4/row
    out[idx0 + 16385]   = v1;
}

extern "C" void kernel_launch(void* const* d_in, const int* in_sizes, int n_in,
                              void* d_out, int out_size) {
    // Locate code_book by element count (65536); all four sizes are distinct.
    const float* code_book = nullptr;
    for (int i = 0; i < n_in; ++i) {
        if (in_sizes[i] == C * Qdim) { code_book = (const float*)d_in[i]; break; }
    }
    if (!code_book) code_book = (const float*)d_in[2];

    (void)out_size;  // 524288 floats = 2048 rows x 256 cols, covered exactly
    fused_rpq_kernel<<<128, 256>>>(code_book, reinterpret_cast<float4*>(d_out));
}

// round 6
// speedup vs baseline: 1.0337x; 1.0337x over previous
#include <cuda_runtime.h>

// labels[c] = argmax_q code_book[c][q]  (first-occurrence tie-break)
//   == reference argmin_q (tn[b,l,c] - cbn[c,q]): tn is constant over q and
//   cbn is a monotone strictly-increasing affine map of code_book, so the
//   GEMM, both LayerNorms, and the (B,L,C,Q) distance tensor are dead code.
// Output (B,L,C)=(4,512,256) f32: every row is a copy of labels[0..255].
//
// Two kernels linked by Programmatic Dependent Launch: the broadcast kernel
// launches concurrently with the argmax kernel, overlaps its ramp/address
// math, then cudaGridDependencySynchronize() waits for the labels.

static constexpr int C    = 256;
static constexpr int Qdim = 256;

__device__ __align__(16) float g_labels_f[C];

// ---- Producer: one warp per codebook row (32 blocks x 8 warps) ----
__global__ void __launch_bounds__(256, 1)
argmax_kernel(const float* __restrict__ cb) {
    const int lane = threadIdx.x & 31;
    const int warp = threadIdx.x >> 5;
    const int row  = blockIdx.x * 8 + warp;

    const float4* __restrict__ rp =
        reinterpret_cast<const float4*>(cb + row * Qdim) + lane * 2;
    const float4 a = __ldg(rp);
    const float4 b = __ldg(rp + 1);

    // per-lane best over q = 8*lane .. 8*lane+7 (strict > keeps first index)
    float bv = a.x; int bi = 0;
    if (a.y > bv) { bv = a.y; bi = 1; }
    if (a.z > bv) { bv = a.z; bi = 2; }
    if (a.w > bv) { bv = a.w; bi = 3; }
    if (b.x > bv) { bv = b.x; bi = 4; }
    if (b.y > bv) { bv = b.y; bi = 5; }
    if (b.z > bv) { bv = b.z; bi = 6; }
    if (b.w > bv) { bv = b.w; bi = 7; }
    bi += lane * 8;

    // order-preserving bijection f32 -> u32, REDUX.MAX, first-lane tie-break
    const unsigned u    = __float_as_uint(bv);
    const unsigned skey = u ^ (unsigned)(((int)u >> 31) | 0x80000000);
    const unsigned m    = __reduce_max_sync(0xffffffffu, skey);
    const unsigned mask = __ballot_sync(0xffffffffu, skey == m);
    const int src       = __ffs(mask) - 1;   // lowest lane = lowest q range
    const int win       = __shfl_sync(0xffffffffu, bi, src);
    if (lane == 0) g_labels_f[row] = (float)win;

    // Let the dependent grid start as early as possible.
    cudaTriggerProgrammaticLaunchCompletion();
}

// ---- Consumer: widest possible store drain, 1 STG.128 per thread ----
__global__ void __launch_bounds__(256, 8)
broadcast_kernel(float4* __restrict__ out, int n4) {
    const int idx = blockIdx.x * blockDim.x + threadIdx.x;   // ramp + math first
    const int src = idx & (C / 4 - 1);

    cudaGridDependencySynchronize();   // wait for argmax_kernel's stores

    const float4* __restrict__ lab4 =
        reinterpret_cast<const float4*>(g_labels_f);
    if (idx < n4) out[idx] = lab4[src];
}

extern "C" void kernel_launch(void* const* d_in, const int* in_sizes, int n_in,
                              void* d_out, int out_size) {
    // Locate code_book by element count (65536); all four sizes are distinct.
    const float* code_book = nullptr;
    for (int i = 0; i < n_in; ++i) {
        if (in_sizes[i] == C * Qdim) { code_book = (const float*)d_in[i]; break; }
    }
    if (!code_book) code_book = (const float*)d_in[2];

    argmax_kernel<<<32, 256>>>(code_book);

    // Broadcast with PDL: launches alongside argmax, syncs inside.
    const int n4 = out_size / 4;   // 131072 float4
    cudaLaunchConfig_t cfg = {};
    cfg.gridDim  = dim3(512, 1, 1);
    cfg.blockDim = dim3(256, 1, 1);
    cudaLaunchAttribute attr[1];
    attr[0].id = cudaLaunchAttributeProgrammaticStreamSerialization;
    attr[0].val.programmaticStreamSerializationAllowed = 1;
    cfg.attrs    = attr;
    cfg.numAttrs = 1;
    cudaLaunchKernelEx(&cfg, broadcast_kernel,
                       reinterpret_cast<float4*>(d_out), n4);
}